// round 11
// baseline (speedup 1.0000x reference)
#include <cuda_runtime.h>

#define NNODES 50000
#define NEDGES 800000
#define FDIM 64
#define NCLS 16
#define CAP 128   // per-node edge capacity (deg ~ Binomial(800k,1/50k); max ~45)

typedef unsigned long long ull;

// ---- device scratch (allocation-free) ----
__device__ int   g_cnt[NNODES];                  // per-node fill counters
__device__ float g_degw[NNODES];                 // weighted degree
__device__ float g_dinv[NNODES];
__device__ int2  g_edge[(size_t)NNODES * CAP];   // bucketed edges: {src, w bits}
__device__ float g_bufA[(size_t)NNODES * FDIM];  // layer-1 output
__device__ float g_bufB[(size_t)NNODES * FDIM];  // layer-2 output

// ---------------- prologue ----------------
__global__ void k_prep(int n) {
    int i = blockIdx.x * blockDim.x + threadIdx.x;
    if (i < n) { g_cnt[i] = 0; g_degw[i] = 1.0f; }  // 1.0 = self-loop weight
}

__global__ void k_edge(const int* __restrict__ ei,
                       const float* __restrict__ w, int e) {
    int i = blockIdx.x * blockDim.x + threadIdx.x;
    if (i < e) {
        int   r  = ei[i];
        int   c  = ei[e + i];
        float wv = w[i];
        atomicAdd(&g_degw[c], wv);
        int pos = atomicAdd(&g_cnt[c], 1);
        if (pos < CAP)
            g_edge[(size_t)c * CAP + pos] = make_int2(r, __float_as_int(wv));
    }
}

__global__ void k_dinv(int n) {
    int i = blockIdx.x * blockDim.x + threadIdx.x;
    if (i < n) {
        float d = g_degw[i];
        g_dinv[i] = (d > 0.0f) ? rsqrtf(d) : 0.0f;
    }
}

// ---------------- fused layer: Y = relu( (Â·Xsrc) @ W + bias ) ----------------
// L==1: Xsrc = Xext (kernel param), Y = g_bufA
// L==2: Xsrc = g_bufA,              Y = g_bufB
// (device-global buffers bound IN DEVICE CODE — never passed from host)
//
// Block = 64 nodes, 256 threads.
// Phase 1: 64 nodes x 4 lanes; each lane owns 4 consecutive float4s (64 B) of
//          its node's feature row -> per-edge MLP of 4 LDG.128 per lane, all 64
//          node chains run concurrently (no serial s-loop). Result written to
//          smem transposed with XOR swizzle ZT[k][row ^ (k & 60)].
// Phase 2: row-packed 4x4 register-tile GEMM from smem (fma.rn.f32x2),
//          bias + relu fused into the epilogue.
template <int L>
__global__ void __launch_bounds__(256) k_layer(const float* __restrict__ Xext,
                                               const float* __restrict__ bias,
                                               const float* __restrict__ W, int n) {
    __shared__ __align__(16) float Ws[FDIM * FDIM];   // [k][c]
    __shared__ __align__(16) float ZT[FDIM][68];      // [k][node^], padded
    const int tid = threadIdx.x;

    const float* Xsrc = (L == 1) ? Xext : g_bufA;
    float*       Y    = (L == 1) ? g_bufA : g_bufB;

    // load W (float4 copy)
    {
        const float4* W4 = (const float4*)W;
        float4* Ws4 = (float4*)Ws;
#pragma unroll
        for (int i = tid; i < FDIM * FDIM / 4; i += 256)
            Ws4[i] = W4[i];
    }

    const int row0 = blockIdx.x * 64;
    const int rr   = tid >> 2;      // local node 0..63
    const int qg   = tid & 3;       // quarter of the feature row (4 float4s)
    const int node = row0 + rr;

    // ---- Phase 1: aggregation (all 64 nodes in parallel) ----
    float4 acc0 = make_float4(0.f, 0.f, 0.f, 0.f);
    float4 acc1 = acc0, acc2 = acc0, acc3 = acc0;
    if (node < n) {
        int cnt = g_cnt[node];
        if (cnt > CAP) cnt = CAP;
        float dv = g_dinv[node];
        const size_t base = (size_t)node * CAP;

        const float4* xself = reinterpret_cast<const float4*>(Xsrc + (size_t)node * FDIM) + qg * 4;
        float4 a0 = __ldg(xself + 0), a1 = __ldg(xself + 1);
        float4 a2 = __ldg(xself + 2), a3 = __ldg(xself + 3);
        acc0 = make_float4(a0.x * dv, a0.y * dv, a0.z * dv, a0.w * dv);
        acc1 = make_float4(a1.x * dv, a1.y * dv, a1.z * dv, a1.w * dv);
        acc2 = make_float4(a2.x * dv, a2.y * dv, a2.z * dv, a2.w * dv);
        acc3 = make_float4(a3.x * dv, a3.y * dv, a3.z * dv, a3.w * dv);

        int i = 0;
        for (; i + 2 <= cnt; i += 2) {
            int2 e0 = __ldg(g_edge + base + i + 0);
            int2 e1 = __ldg(g_edge + base + i + 1);
            float n0 = __ldg(g_dinv + e0.x) * __int_as_float(e0.y);
            float n1 = __ldg(g_dinv + e1.x) * __int_as_float(e1.y);
            const float4* x0 = reinterpret_cast<const float4*>(Xsrc + (size_t)e0.x * FDIM) + qg * 4;
            const float4* x1 = reinterpret_cast<const float4*>(Xsrc + (size_t)e1.x * FDIM) + qg * 4;
            float4 v00 = __ldg(x0 + 0), v01 = __ldg(x0 + 1), v02 = __ldg(x0 + 2), v03 = __ldg(x0 + 3);
            float4 v10 = __ldg(x1 + 0), v11 = __ldg(x1 + 1), v12 = __ldg(x1 + 2), v13 = __ldg(x1 + 3);
            acc0.x += n0 * v00.x + n1 * v10.x;  acc0.y += n0 * v00.y + n1 * v10.y;
            acc0.z += n0 * v00.z + n1 * v10.z;  acc0.w += n0 * v00.w + n1 * v10.w;
            acc1.x += n0 * v01.x + n1 * v11.x;  acc1.y += n0 * v01.y + n1 * v11.y;
            acc1.z += n0 * v01.z + n1 * v11.z;  acc1.w += n0 * v01.w + n1 * v11.w;
            acc2.x += n0 * v02.x + n1 * v12.x;  acc2.y += n0 * v02.y + n1 * v12.y;
            acc2.z += n0 * v02.z + n1 * v12.z;  acc2.w += n0 * v02.w + n1 * v12.w;
            acc3.x += n0 * v03.x + n1 * v13.x;  acc3.y += n0 * v03.y + n1 * v13.y;
            acc3.z += n0 * v03.z + n1 * v13.z;  acc3.w += n0 * v03.w + n1 * v13.w;
        }
        if (i < cnt) {
            int2 e0 = __ldg(g_edge + base + i);
            float n0 = __ldg(g_dinv + e0.x) * __int_as_float(e0.y);
            const float4* x0 = reinterpret_cast<const float4*>(Xsrc + (size_t)e0.x * FDIM) + qg * 4;
            float4 v00 = __ldg(x0 + 0), v01 = __ldg(x0 + 1), v02 = __ldg(x0 + 2), v03 = __ldg(x0 + 3);
            acc0.x += n0 * v00.x;  acc0.y += n0 * v00.y;  acc0.z += n0 * v00.z;  acc0.w += n0 * v00.w;
            acc1.x += n0 * v01.x;  acc1.y += n0 * v01.y;  acc1.z += n0 * v01.z;  acc1.w += n0 * v01.w;
            acc2.x += n0 * v02.x;  acc2.y += n0 * v02.y;  acc2.z += n0 * v02.z;  acc2.w += n0 * v02.w;
            acc3.x += n0 * v03.x;  acc3.y += n0 * v03.y;  acc3.z += n0 * v03.z;  acc3.w += n0 * v03.w;
        }
        acc0.x *= dv; acc0.y *= dv; acc0.z *= dv; acc0.w *= dv;
        acc1.x *= dv; acc1.y *= dv; acc1.z *= dv; acc1.w *= dv;
        acc2.x *= dv; acc2.y *= dv; acc2.z *= dv; acc2.w *= dv;
        acc3.x *= dv; acc3.y *= dv; acc3.z *= dv; acc3.w *= dv;
    }
    // store to ZT with XOR swizzle; (kk+c)&60 == kk&60 since kk is 4-aligned
    {
        int kk0 = qg * 16;
        float4 av[4] = {acc0, acc1, acc2, acc3};
#pragma unroll
        for (int j = 0; j < 4; j++) {
            int kk  = kk0 + j * 4;
            int col = rr ^ (kk & 60);
            ZT[kk + 0][col] = av[j].x;
            ZT[kk + 1][col] = av[j].y;
            ZT[kk + 2][col] = av[j].z;
            ZT[kk + 3][col] = av[j].w;
        }
    }
    __syncthreads();

    // ---- Phase 2: GEMM from smem, 4 rows x 4 cols per thread ----
    const int c0 = (tid & 15) * 4;
    const int r0 = (tid >> 4) * 4;

    ull acc01[4] = {0ull, 0ull, 0ull, 0ull};   // rows (r0, r0+1), cols c0..c0+3
    ull acc23[4] = {0ull, 0ull, 0ull, 0ull};   // rows (r0+2, r0+3)

#pragma unroll
    for (int k = 0; k < FDIM; k++) {
        int rsw = r0 ^ (k & 60);
        ulonglong2 av = *(const ulonglong2*)&ZT[k][rsw];   // this thread's row pairs
        float4 bv = *(const float4*)&Ws[k * FDIM + c0];
        ull bd0, bd1, bd2, bd3;
        asm("mov.b64 %0, {%1, %1};" : "=l"(bd0) : "f"(bv.x));
        asm("mov.b64 %0, {%1, %1};" : "=l"(bd1) : "f"(bv.y));
        asm("mov.b64 %0, {%1, %1};" : "=l"(bd2) : "f"(bv.z));
        asm("mov.b64 %0, {%1, %1};" : "=l"(bd3) : "f"(bv.w));
        asm("fma.rn.f32x2 %0, %1, %2, %0;" : "+l"(acc01[0]) : "l"(av.x), "l"(bd0));
        asm("fma.rn.f32x2 %0, %1, %2, %0;" : "+l"(acc01[1]) : "l"(av.x), "l"(bd1));
        asm("fma.rn.f32x2 %0, %1, %2, %0;" : "+l"(acc01[2]) : "l"(av.x), "l"(bd2));
        asm("fma.rn.f32x2 %0, %1, %2, %0;" : "+l"(acc01[3]) : "l"(av.x), "l"(bd3));
        asm("fma.rn.f32x2 %0, %1, %2, %0;" : "+l"(acc23[0]) : "l"(av.y), "l"(bd0));
        asm("fma.rn.f32x2 %0, %1, %2, %0;" : "+l"(acc23[1]) : "l"(av.y), "l"(bd1));
        asm("fma.rn.f32x2 %0, %1, %2, %0;" : "+l"(acc23[2]) : "l"(av.y), "l"(bd2));
        asm("fma.rn.f32x2 %0, %1, %2, %0;" : "+l"(acc23[3]) : "l"(av.y), "l"(bd3));
    }

    // epilogue: unpack row pairs, add bias, relu, store float4 per row
    float4 b4 = *(const float4*)&bias[c0];
    float r0v[4], r1v[4], r2v[4], r3v[4];
#pragma unroll
    for (int c = 0; c < 4; c++) {
        asm("mov.b64 {%0, %1}, %2;" : "=f"(r0v[c]), "=f"(r1v[c]) : "l"(acc01[c]));
        asm("mov.b64 {%0, %1}, %2;" : "=f"(r2v[c]), "=f"(r3v[c]) : "l"(acc23[c]));
    }
    float4 o0 = make_float4(fmaxf(r0v[0] + b4.x, 0.f), fmaxf(r0v[1] + b4.y, 0.f),
                            fmaxf(r0v[2] + b4.z, 0.f), fmaxf(r0v[3] + b4.w, 0.f));
    float4 o1 = make_float4(fmaxf(r1v[0] + b4.x, 0.f), fmaxf(r1v[1] + b4.y, 0.f),
                            fmaxf(r1v[2] + b4.z, 0.f), fmaxf(r1v[3] + b4.w, 0.f));
    float4 o2 = make_float4(fmaxf(r2v[0] + b4.x, 0.f), fmaxf(r2v[1] + b4.y, 0.f),
                            fmaxf(r2v[2] + b4.z, 0.f), fmaxf(r2v[3] + b4.w, 0.f));
    float4 o3 = make_float4(fmaxf(r3v[0] + b4.x, 0.f), fmaxf(r3v[1] + b4.y, 0.f),
                            fmaxf(r3v[2] + b4.z, 0.f), fmaxf(r3v[3] + b4.w, 0.f));
    int row = row0 + r0;
    if (row + 0 < n) *(float4*)&Y[(size_t)(row + 0) * FDIM + c0] = o0;
    if (row + 1 < n) *(float4*)&Y[(size_t)(row + 1) * FDIM + c0] = o1;
    if (row + 2 < n) *(float4*)&Y[(size_t)(row + 2) * FDIM + c0] = o2;
    if (row + 3 < n) *(float4*)&Y[(size_t)(row + 3) * FDIM + c0] = o3;
}

// ---------------- head: bufB @ Wout + bout -> softmax ----------------
// (bias b2 + relu already applied by layer 2's epilogue)
__global__ void k_head(const float* __restrict__ Wout,
                       const float* __restrict__ bout,
                       float* __restrict__ out, int n) {
    __shared__ float Ws[FDIM * NCLS];
    __shared__ float Hs[8][FDIM + 1];
    const int tid = threadIdx.x;   // 0..127

    for (int i = tid; i < FDIM * NCLS; i += 128) Ws[i] = Wout[i];

    int row0 = blockIdx.x * 8;
    for (int i = tid; i < 8 * FDIM; i += 128) {
        int rr = i >> 6, k = i & 63;
        int row = row0 + rr;
        Hs[rr][k] = (row < n) ? g_bufB[(size_t)row * FDIM + k] : 0.0f;
    }
    __syncthreads();

    int rr = tid >> 4;
    int c  = tid & 15;
    int row = row0 + rr;
    if (row < n) {
        float acc = bout[c];
#pragma unroll
        for (int k = 0; k < FDIM; k++)
            acc += Hs[rr][k] * Ws[k * NCLS + c];
        float m = acc;
#pragma unroll
        for (int off = 8; off; off >>= 1)
            m = fmaxf(m, __shfl_xor_sync(0xffffffffu, m, off, 16));
        float ex = __expf(acc - m);
        float s = ex;
#pragma unroll
        for (int off = 8; off; off >>= 1)
            s += __shfl_xor_sync(0xffffffffu, s, off, 16);
        out[(size_t)row * NCLS + c] = ex / s;
    }
}

// ---------------- launch ----------------
extern "C" void kernel_launch(void* const* d_in, const int* in_sizes, int n_in,
                              void* d_out, int out_size) {
    const float* x    = (const float*)d_in[0];
    const int*   ei   = (const int*)d_in[1];    // int32 (JAX x64 disabled)
    const float* w    = (const float*)d_in[2];
    const float* W1   = (const float*)d_in[3];
    const float* b1   = (const float*)d_in[4];
    const float* W2   = (const float*)d_in[5];
    const float* b2   = (const float*)d_in[6];
    const float* Wout = (const float*)d_in[7];
    const float* bout = (const float*)d_in[8];
    float*       out  = (float*)d_out;

    const int n = in_sizes[0] / FDIM;   // 50000
    const int e = in_sizes[2];          // 800000

    const int TB = 256;
    int layerGrid = (n + 63) / 64;

    // prologue: bucket edges + weighted degree, dinv
    k_prep<<<(n + TB - 1) / TB, TB>>>(n);
    k_edge<<<(e + TB - 1) / TB, TB>>>(ei, w, e);
    k_dinv<<<(n + TB - 1) / TB, TB>>>(n);

    // layer 1: g_bufA = relu((Â·x)·W1 + b1)     (buffers bound in device code)
    k_layer<1><<<layerGrid, 256>>>(x, b1, W1, n);
    // layer 2: g_bufB = relu((Â·g_bufA)·W2 + b2)
    k_layer<2><<<layerGrid, 256>>>(x, b2, W2, n);

    // head: softmax(g_bufB·Wout + bout)
    k_head<<<(n + 7) / 8, 128>>>(Wout, bout, out, n);
}

// round 12
// speedup vs baseline: 1.2420x; 1.2420x over previous
#include <cuda_runtime.h>

#define NNODES 50000
#define NEDGES 800000
#define FDIM 64
#define NCLS 16
#define CAP 128   // per-node edge capacity (deg ~ Binomial(800k,1/50k); max ~45)

// ---- device scratch (allocation-free) ----
__device__ int   g_cnt[NNODES];                  // per-node fill counters
__device__ float g_degw[NNODES];                 // weighted degree
__device__ float g_dinv[NNODES];
__device__ int2  g_edge[(size_t)NNODES * CAP];   // bucketed edges: {src, w bits}
__device__ float g_bufA[(size_t)NNODES * FDIM];  // GEMM outputs (gather source)
__device__ float g_bufB[(size_t)NNODES * FDIM];  // aggregated features

// ---------------- prologue ----------------
__global__ void k_prep(int n) {
    int i = blockIdx.x * blockDim.x + threadIdx.x;
    if (i < n) { g_cnt[i] = 0; g_degw[i] = 1.0f; }  // 1.0 = self-loop weight
}

__global__ void k_edge(const int* __restrict__ ei,
                       const float* __restrict__ w, int e) {
    int i = blockIdx.x * blockDim.x + threadIdx.x;
    if (i < e) {
        int   r  = ei[i];
        int   c  = ei[e + i];
        float wv = w[i];
        atomicAdd(&g_degw[c], wv);
        int pos = atomicAdd(&g_cnt[c], 1);
        if (pos < CAP)
            g_edge[(size_t)c * CAP + pos] = make_int2(r, __float_as_int(wv));
    }
}

__global__ void k_dinv(int n) {
    int i = blockIdx.x * blockDim.x + threadIdx.x;
    if (i < n) {
        float d = g_degw[i];
        g_dinv[i] = (d > 0.0f) ? rsqrtf(d) : 0.0f;
    }
}

// ---------------- 64x64 GEMM: bufA = act(X [+bias]) @ W ----------------
// 32 rows/block, 128 threads, 4x4 register tile, packed fma.rn.f32x2.
// (R6 kernel, measured 18.3us — unchanged)
template <bool FROM_BUF>
__global__ void __launch_bounds__(128) k_gemm64(const float* __restrict__ Xext,
                         const float* __restrict__ bias,
                         const float* __restrict__ W, int n) {
    __shared__ __align__(16) float Ws[FDIM * FDIM];   // [k][c] row-major
    __shared__ __align__(16) float XsT[FDIM][36];     // [k][row] transposed, 32 rows + pad
    const int tid = threadIdx.x;                      // 0..127

    {
        const float4* W4 = (const float4*)W;
        float4* Ws4 = (float4*)Ws;
#pragma unroll
        for (int i = tid; i < FDIM * FDIM / 4; i += 128)
            Ws4[i] = W4[i];
    }

    const int row0 = blockIdx.x * 32;
    const float* X = FROM_BUF ? g_bufB : Xext;
    {
        const int kq = tid & 15;
        float4 b4 = make_float4(0.f, 0.f, 0.f, 0.f);
        if (FROM_BUF) b4 = *(const float4*)&bias[kq * 4];
#pragma unroll
        for (int i = tid; i < 32 * 16; i += 128) {
            int rr = i >> 4;
            int row = row0 + rr;
            float4 v = make_float4(0.f, 0.f, 0.f, 0.f);
            if (row < n) v = *(const float4*)&X[(size_t)row * FDIM + kq * 4];
            if (FROM_BUF) {
                v.x = fmaxf(v.x + b4.x, 0.f);
                v.y = fmaxf(v.y + b4.y, 0.f);
                v.z = fmaxf(v.z + b4.z, 0.f);
                v.w = fmaxf(v.w + b4.w, 0.f);
            }
            XsT[kq * 4 + 0][rr] = v.x;
            XsT[kq * 4 + 1][rr] = v.y;
            XsT[kq * 4 + 2][rr] = v.z;
            XsT[kq * 4 + 3][rr] = v.w;
        }
    }
    __syncthreads();

    const int c0 = (tid & 15) * 4;   // 4 output cols
    const int r0 = (tid >> 4) * 4;   // 4 rows within tile

    unsigned long long acc01[4] = {0ull, 0ull, 0ull, 0ull};
    unsigned long long acc23[4] = {0ull, 0ull, 0ull, 0ull};

#pragma unroll
    for (int k = 0; k < FDIM; k++) {
        ulonglong2 av = *(const ulonglong2*)&XsT[k][r0];
        float4 bv = *(const float4*)&Ws[k * FDIM + c0];
        unsigned long long bd0, bd1, bd2, bd3;
        asm("mov.b64 %0, {%1, %1};" : "=l"(bd0) : "f"(bv.x));
        asm("mov.b64 %0, {%1, %1};" : "=l"(bd1) : "f"(bv.y));
        asm("mov.b64 %0, {%1, %1};" : "=l"(bd2) : "f"(bv.z));
        asm("mov.b64 %0, {%1, %1};" : "=l"(bd3) : "f"(bv.w));
        asm("fma.rn.f32x2 %0, %1, %2, %0;" : "+l"(acc01[0]) : "l"(av.x), "l"(bd0));
        asm("fma.rn.f32x2 %0, %1, %2, %0;" : "+l"(acc01[1]) : "l"(av.x), "l"(bd1));
        asm("fma.rn.f32x2 %0, %1, %2, %0;" : "+l"(acc01[2]) : "l"(av.x), "l"(bd2));
        asm("fma.rn.f32x2 %0, %1, %2, %0;" : "+l"(acc01[3]) : "l"(av.x), "l"(bd3));
        asm("fma.rn.f32x2 %0, %1, %2, %0;" : "+l"(acc23[0]) : "l"(av.y), "l"(bd0));
        asm("fma.rn.f32x2 %0, %1, %2, %0;" : "+l"(acc23[1]) : "l"(av.y), "l"(bd1));
        asm("fma.rn.f32x2 %0, %1, %2, %0;" : "+l"(acc23[2]) : "l"(av.y), "l"(bd2));
        asm("fma.rn.f32x2 %0, %1, %2, %0;" : "+l"(acc23[3]) : "l"(av.y), "l"(bd3));
    }

    float lo[4], hi[4], lo2[4], hi2[4];
#pragma unroll
    for (int c = 0; c < 4; c++) {
        asm("mov.b64 {%0, %1}, %2;" : "=f"(lo[c]),  "=f"(hi[c])  : "l"(acc01[c]));
        asm("mov.b64 {%0, %1}, %2;" : "=f"(lo2[c]), "=f"(hi2[c]) : "l"(acc23[c]));
    }
    int row = row0 + r0;
    if (row + 0 < n) *(float4*)&g_bufA[(size_t)(row + 0) * FDIM + c0] = make_float4(lo[0],  lo[1],  lo[2],  lo[3]);
    if (row + 1 < n) *(float4*)&g_bufA[(size_t)(row + 1) * FDIM + c0] = make_float4(hi[0],  hi[1],  hi[2],  hi[3]);
    if (row + 2 < n) *(float4*)&g_bufA[(size_t)(row + 2) * FDIM + c0] = make_float4(lo2[0], lo2[1], lo2[2], lo2[3]);
    if (row + 3 < n) *(float4*)&g_bufA[(size_t)(row + 3) * FDIM + c0] = make_float4(hi2[0], hi2[1], hi2[2], hi2[3]);
}

// ---------------- pull aggregation: bufB[v] = dv*( sum dinv[src]*w*bufA[src] + dv*bufA[v] ) ----------------
// 16 lanes per node, one float4 per lane; int2-packed edges; unroll 8 for MLP.
__global__ void k_agg_pull(int n) {
    int gid = blockIdx.x * blockDim.x + threadIdx.x;
    int node = gid >> 4;
    int q    = gid & 15;
    if (node >= n) return;

    int cnt = g_cnt[node];
    if (cnt > CAP) cnt = CAP;
    float dv = g_dinv[node];
    const size_t base = (size_t)node * CAP;

    float4 a = __ldg(reinterpret_cast<const float4*>(g_bufA + (size_t)node * FDIM) + q);
    float4 acc = make_float4(a.x * dv, a.y * dv, a.z * dv, a.w * dv);

    int i = 0;
    for (; i + 8 <= cnt; i += 8) {
        int2 e[8];
#pragma unroll
        for (int j = 0; j < 8; j++) e[j] = __ldg(g_edge + base + i + j);
        float nv[8];
#pragma unroll
        for (int j = 0; j < 8; j++) nv[j] = __ldg(g_dinv + e[j].x) * __int_as_float(e[j].y);
        float4 xv[8];
#pragma unroll
        for (int j = 0; j < 8; j++)
            xv[j] = __ldg(reinterpret_cast<const float4*>(g_bufA + (size_t)e[j].x * FDIM) + q);
#pragma unroll
        for (int j = 0; j < 8; j++) {
            acc.x += nv[j] * xv[j].x;
            acc.y += nv[j] * xv[j].y;
            acc.z += nv[j] * xv[j].z;
            acc.w += nv[j] * xv[j].w;
        }
    }
    for (; i < cnt; i++) {
        int2 e0 = __ldg(g_edge + base + i);
        float n0 = __ldg(g_dinv + e0.x) * __int_as_float(e0.y);
        float4 x0 = __ldg(reinterpret_cast<const float4*>(g_bufA + (size_t)e0.x * FDIM) + q);
        acc.x += n0 * x0.x;
        acc.y += n0 * x0.y;
        acc.z += n0 * x0.z;
        acc.w += n0 * x0.w;
    }
    acc.x *= dv; acc.y *= dv; acc.z *= dv; acc.w *= dv;
    reinterpret_cast<float4*>(g_bufB + (size_t)node * FDIM)[q] = acc;
}

// ---------------- head: relu(bufB + b2) @ Wout + bout -> softmax ----------------
__global__ void k_head(const float* __restrict__ b2,
                       const float* __restrict__ Wout,
                       const float* __restrict__ bout,
                       float* __restrict__ out, int n) {
    __shared__ float Ws[FDIM * NCLS];
    __shared__ float Hs[8][FDIM + 1];
    const int tid = threadIdx.x;   // 0..127

    for (int i = tid; i < FDIM * NCLS; i += 128) Ws[i] = Wout[i];

    int row0 = blockIdx.x * 8;
    for (int i = tid; i < 8 * FDIM; i += 128) {
        int rr = i >> 6, k = i & 63;
        int row = row0 + rr;
        float v = (row < n) ? g_bufB[(size_t)row * FDIM + k] : 0.0f;
        Hs[rr][k] = fmaxf(v + b2[k], 0.0f);
    }
    __syncthreads();

    int rr = tid >> 4;
    int c  = tid & 15;
    int row = row0 + rr;
    if (row < n) {
        float acc = bout[c];
#pragma unroll
        for (int k = 0; k < FDIM; k++)
            acc += Hs[rr][k] * Ws[k * NCLS + c];
        float m = acc;
#pragma unroll
        for (int off = 8; off; off >>= 1)
            m = fmaxf(m, __shfl_xor_sync(0xffffffffu, m, off, 16));
        float ex = __expf(acc - m);
        float s = ex;
#pragma unroll
        for (int off = 8; off; off >>= 1)
            s += __shfl_xor_sync(0xffffffffu, s, off, 16);
        out[(size_t)row * NCLS + c] = ex / s;
    }
}

// ---------------- launch ----------------
extern "C" void kernel_launch(void* const* d_in, const int* in_sizes, int n_in,
                              void* d_out, int out_size) {
    const float* x    = (const float*)d_in[0];
    const int*   ei   = (const int*)d_in[1];    // int32 (JAX x64 disabled)
    const float* w    = (const float*)d_in[2];
    const float* W1   = (const float*)d_in[3];
    const float* b1   = (const float*)d_in[4];
    const float* W2   = (const float*)d_in[5];
    const float* b2   = (const float*)d_in[6];
    const float* Wout = (const float*)d_in[7];
    const float* bout = (const float*)d_in[8];
    float*       out  = (float*)d_out;

    const int n = in_sizes[0] / FDIM;   // 50000
    const int e = in_sizes[2];          // 800000

    const int TB = 256;
    int gemmGrid = (n + 31) / 32;
    int lanGrid  = (int)(((size_t)n * 16 + TB - 1) / TB);

    // prologue: bucket edges + weighted degree, dinv
    k_prep<<<(n + TB - 1) / TB, TB>>>(n);
    k_edge<<<(e + TB - 1) / TB, TB>>>(ei, w, e);
    k_dinv<<<(n + TB - 1) / TB, TB>>>(n);

    // layer 1
    k_gemm64<false><<<gemmGrid, 128>>>(x, b1, W1, n);
    k_agg_pull<<<lanGrid, TB>>>(n);

    // layer 2 (bias b1 + relu fused into GEMM load)
    k_gemm64<true><<<gemmGrid, 128>>>(x, b1, W2, n);
    k_agg_pull<<<lanGrid, TB>>>(n);

    // head: bias b2 + relu + GEMM->16 + softmax
    k_head<<<(n + 7) / 8, 128>>>(b2, Wout, bout, out, n);
}

// round 13
// speedup vs baseline: 1.2653x; 1.0188x over previous
#include <cuda_runtime.h>
#include <cuda_fp16.h>

#define NNODES 50000
#define NEDGES 800000
#define FDIM 64
#define NCLS 16
#define CAP 128   // per-node edge capacity (deg ~ Binomial(800k,1/50k); max ~45)

// ---- device scratch (allocation-free) ----
__device__ int    g_cnt[NNODES];                   // per-node fill counters
__device__ float  g_degw[NNODES];                  // weighted degree
__device__ float  g_dinv[NNODES];
__device__ int2   g_edge[(size_t)NNODES * CAP];    // bucketed edges: {src, w bits}
__device__ __half g_bufAh[(size_t)NNODES * FDIM];  // GEMM outputs, fp16 (gather source)
__device__ float  g_bufB[(size_t)NNODES * FDIM];   // aggregated features, fp32

// ---------------- prologue ----------------
__global__ void k_prep(int n) {
    int i = blockIdx.x * blockDim.x + threadIdx.x;
    if (i < n) { g_cnt[i] = 0; g_degw[i] = 1.0f; }  // 1.0 = self-loop weight
}

__global__ void k_edge(const int* __restrict__ ei,
                       const float* __restrict__ w, int e) {
    int i = blockIdx.x * blockDim.x + threadIdx.x;
    if (i < e) {
        int   r  = ei[i];
        int   c  = ei[e + i];
        float wv = w[i];
        atomicAdd(&g_degw[c], wv);
        int pos = atomicAdd(&g_cnt[c], 1);
        if (pos < CAP)
            g_edge[(size_t)c * CAP + pos] = make_int2(r, __float_as_int(wv));
    }
}

__global__ void k_dinv(int n) {
    int i = blockIdx.x * blockDim.x + threadIdx.x;
    if (i < n) {
        float d = g_degw[i];
        g_dinv[i] = (d > 0.0f) ? rsqrtf(d) : 0.0f;
    }
}

// ---------------- 64x64 GEMM: bufAh = fp16( act(X [+bias]) @ W ) ----------------
// 64 rows/block, 256 threads, 4x4 register tile per thread, packed fma.rn.f32x2.
template <bool FROM_BUF>
__global__ void __launch_bounds__(256) k_gemm64(const float* __restrict__ Xext,
                         const float* __restrict__ bias,
                         const float* __restrict__ W, int n) {
    __shared__ __align__(16) float Ws[FDIM * FDIM];   // [k][c] row-major
    __shared__ __align__(16) float XsT[FDIM][68];     // [k][row] transposed, 64 rows + pad
    const int tid = threadIdx.x;                      // 0..255

    {
        const float4* W4 = (const float4*)W;
        float4* Ws4 = (float4*)Ws;
#pragma unroll
        for (int i = tid; i < FDIM * FDIM / 4; i += 256)
            Ws4[i] = W4[i];
    }

    const int row0 = blockIdx.x * 64;
    const float* X = FROM_BUF ? g_bufB : Xext;
    {
        const int kq = tid & 15;
        float4 b4 = make_float4(0.f, 0.f, 0.f, 0.f);
        if (FROM_BUF) b4 = *(const float4*)&bias[kq * 4];
#pragma unroll
        for (int i = tid; i < 64 * 16; i += 256) {
            int rr = i >> 4;
            int row = row0 + rr;
            float4 v = make_float4(0.f, 0.f, 0.f, 0.f);
            if (row < n) v = *(const float4*)&X[(size_t)row * FDIM + kq * 4];
            if (FROM_BUF) {
                v.x = fmaxf(v.x + b4.x, 0.f);
                v.y = fmaxf(v.y + b4.y, 0.f);
                v.z = fmaxf(v.z + b4.z, 0.f);
                v.w = fmaxf(v.w + b4.w, 0.f);
            }
            XsT[kq * 4 + 0][rr] = v.x;
            XsT[kq * 4 + 1][rr] = v.y;
            XsT[kq * 4 + 2][rr] = v.z;
            XsT[kq * 4 + 3][rr] = v.w;
        }
    }
    __syncthreads();

    const int c0 = (tid & 15) * 4;   // 4 output cols
    const int r0 = (tid >> 4) * 4;   // 4 rows within tile (0..60)

    unsigned long long acc01[4] = {0ull, 0ull, 0ull, 0ull};
    unsigned long long acc23[4] = {0ull, 0ull, 0ull, 0ull};

#pragma unroll
    for (int k = 0; k < FDIM; k++) {
        ulonglong2 av = *(const ulonglong2*)&XsT[k][r0];
        float4 bv = *(const float4*)&Ws[k * FDIM + c0];
        unsigned long long bd0, bd1, bd2, bd3;
        asm("mov.b64 %0, {%1, %1};" : "=l"(bd0) : "f"(bv.x));
        asm("mov.b64 %0, {%1, %1};" : "=l"(bd1) : "f"(bv.y));
        asm("mov.b64 %0, {%1, %1};" : "=l"(bd2) : "f"(bv.z));
        asm("mov.b64 %0, {%1, %1};" : "=l"(bd3) : "f"(bv.w));
        asm("fma.rn.f32x2 %0, %1, %2, %0;" : "+l"(acc01[0]) : "l"(av.x), "l"(bd0));
        asm("fma.rn.f32x2 %0, %1, %2, %0;" : "+l"(acc01[1]) : "l"(av.x), "l"(bd1));
        asm("fma.rn.f32x2 %0, %1, %2, %0;" : "+l"(acc01[2]) : "l"(av.x), "l"(bd2));
        asm("fma.rn.f32x2 %0, %1, %2, %0;" : "+l"(acc01[3]) : "l"(av.x), "l"(bd3));
        asm("fma.rn.f32x2 %0, %1, %2, %0;" : "+l"(acc23[0]) : "l"(av.y), "l"(bd0));
        asm("fma.rn.f32x2 %0, %1, %2, %0;" : "+l"(acc23[1]) : "l"(av.y), "l"(bd1));
        asm("fma.rn.f32x2 %0, %1, %2, %0;" : "+l"(acc23[2]) : "l"(av.y), "l"(bd2));
        asm("fma.rn.f32x2 %0, %1, %2, %0;" : "+l"(acc23[3]) : "l"(av.y), "l"(bd3));
    }

    // epilogue: unpack row pairs, convert to fp16, one 8B store per row
    float lo[4], hi[4], lo2[4], hi2[4];
#pragma unroll
    for (int c = 0; c < 4; c++) {
        asm("mov.b64 {%0, %1}, %2;" : "=f"(lo[c]),  "=f"(hi[c])  : "l"(acc01[c]));
        asm("mov.b64 {%0, %1}, %2;" : "=f"(lo2[c]), "=f"(hi2[c]) : "l"(acc23[c]));
    }
    int row = row0 + r0;
    __half2 h[2];
    if (row + 0 < n) {
        h[0] = __float22half2_rn(make_float2(lo[0], lo[1]));
        h[1] = __float22half2_rn(make_float2(lo[2], lo[3]));
        *(uint2*)&g_bufAh[(size_t)(row + 0) * FDIM + c0] = *(uint2*)h;
    }
    if (row + 1 < n) {
        h[0] = __float22half2_rn(make_float2(hi[0], hi[1]));
        h[1] = __float22half2_rn(make_float2(hi[2], hi[3]));
        *(uint2*)&g_bufAh[(size_t)(row + 1) * FDIM + c0] = *(uint2*)h;
    }
    if (row + 2 < n) {
        h[0] = __float22half2_rn(make_float2(lo2[0], lo2[1]));
        h[1] = __float22half2_rn(make_float2(lo2[2], lo2[3]));
        *(uint2*)&g_bufAh[(size_t)(row + 2) * FDIM + c0] = *(uint2*)h;
    }
    if (row + 3 < n) {
        h[0] = __float22half2_rn(make_float2(hi2[0], hi2[1]));
        h[1] = __float22half2_rn(make_float2(hi2[2], hi2[3]));
        *(uint2*)&g_bufAh[(size_t)(row + 3) * FDIM + c0] = *(uint2*)h;
    }
}

// fp16x8 gather helper: accumulate nv * bufAh[src][8q .. 8q+7] into acc[8] (fp32)
__device__ __forceinline__ void acc_half8(float* acc, float nv, uint4 u) {
    float2 f0 = __half22float2(*(__half2*)&u.x);
    float2 f1 = __half22float2(*(((__half2*)&u.x) + 1));
    float2 f2 = __half22float2(*(__half2*)&u.z);
    float2 f3 = __half22float2(*(((__half2*)&u.z) + 1));
    acc[0] += nv * f0.x;  acc[1] += nv * f0.y;
    acc[2] += nv * f1.x;  acc[3] += nv * f1.y;
    acc[4] += nv * f2.x;  acc[5] += nv * f2.y;
    acc[6] += nv * f3.x;  acc[7] += nv * f3.y;
}

// ---------------- pull aggregation: bufB[v] = dv*( sum dinv[src]*w*bufAh[src] + dv*bufAh[v] ) ----------------
// 8 lanes per node, one uint4 (8 halves) per lane; fp32 accumulation; unroll 4.
__global__ void k_agg_pull(int n) {
    int gid = blockIdx.x * blockDim.x + threadIdx.x;
    int node = gid >> 3;
    int q    = gid & 7;
    if (node >= n) return;

    int cnt = g_cnt[node];
    if (cnt > CAP) cnt = CAP;
    float dv = g_dinv[node];
    const size_t base = (size_t)node * CAP;
    const uint4* selfp = reinterpret_cast<const uint4*>(g_bufAh + (size_t)node * FDIM) + q;

    float acc[8] = {0.f, 0.f, 0.f, 0.f, 0.f, 0.f, 0.f, 0.f};
    acc_half8(acc, dv, __ldg(selfp));

    int i = 0;
    for (; i + 4 <= cnt; i += 4) {
        int2 e0 = __ldg(g_edge + base + i + 0);
        int2 e1 = __ldg(g_edge + base + i + 1);
        int2 e2 = __ldg(g_edge + base + i + 2);
        int2 e3 = __ldg(g_edge + base + i + 3);
        float n0 = __ldg(g_dinv + e0.x) * __int_as_float(e0.y);
        float n1 = __ldg(g_dinv + e1.x) * __int_as_float(e1.y);
        float n2 = __ldg(g_dinv + e2.x) * __int_as_float(e2.y);
        float n3 = __ldg(g_dinv + e3.x) * __int_as_float(e3.y);
        uint4 u0 = __ldg(reinterpret_cast<const uint4*>(g_bufAh + (size_t)e0.x * FDIM) + q);
        uint4 u1 = __ldg(reinterpret_cast<const uint4*>(g_bufAh + (size_t)e1.x * FDIM) + q);
        uint4 u2 = __ldg(reinterpret_cast<const uint4*>(g_bufAh + (size_t)e2.x * FDIM) + q);
        uint4 u3 = __ldg(reinterpret_cast<const uint4*>(g_bufAh + (size_t)e3.x * FDIM) + q);
        acc_half8(acc, n0, u0);
        acc_half8(acc, n1, u1);
        acc_half8(acc, n2, u2);
        acc_half8(acc, n3, u3);
    }
    for (; i < cnt; i++) {
        int2 e0 = __ldg(g_edge + base + i);
        float n0 = __ldg(g_dinv + e0.x) * __int_as_float(e0.y);
        uint4 u0 = __ldg(reinterpret_cast<const uint4*>(g_bufAh + (size_t)e0.x * FDIM) + q);
        acc_half8(acc, n0, u0);
    }

    float4 o0 = make_float4(acc[0] * dv, acc[1] * dv, acc[2] * dv, acc[3] * dv);
    float4 o1 = make_float4(acc[4] * dv, acc[5] * dv, acc[6] * dv, acc[7] * dv);
    float4* dst = reinterpret_cast<float4*>(g_bufB + (size_t)node * FDIM) + q * 2;
    dst[0] = o0;
    dst[1] = o1;
}

// ---------------- head: relu(bufB + b2) @ Wout + bout -> softmax ----------------
__global__ void k_head(const float* __restrict__ b2,
                       const float* __restrict__ Wout,
                       const float* __restrict__ bout,
                       float* __restrict__ out, int n) {
    __shared__ float Ws[FDIM * NCLS];
    __shared__ float Hs[8][FDIM + 1];
    const int tid = threadIdx.x;   // 0..127

    for (int i = tid; i < FDIM * NCLS; i += 128) Ws[i] = Wout[i];

    int row0 = blockIdx.x * 8;
    for (int i = tid; i < 8 * FDIM; i += 128) {
        int rr = i >> 6, k = i & 63;
        int row = row0 + rr;
        float v = (row < n) ? g_bufB[(size_t)row * FDIM + k] : 0.0f;
        Hs[rr][k] = fmaxf(v + b2[k], 0.0f);
    }
    __syncthreads();

    int rr = tid >> 4;
    int c  = tid & 15;
    int row = row0 + rr;
    if (row < n) {
        float acc = bout[c];
#pragma unroll
        for (int k = 0; k < FDIM; k++)
            acc += Hs[rr][k] * Ws[k * NCLS + c];
        float m = acc;
#pragma unroll
        for (int off = 8; off; off >>= 1)
            m = fmaxf(m, __shfl_xor_sync(0xffffffffu, m, off, 16));
        float ex = __expf(acc - m);
        float s = ex;
#pragma unroll
        for (int off = 8; off; off >>= 1)
            s += __shfl_xor_sync(0xffffffffu, s, off, 16);
        out[(size_t)row * NCLS + c] = ex / s;
    }
}

// ---------------- launch ----------------
extern "C" void kernel_launch(void* const* d_in, const int* in_sizes, int n_in,
                              void* d_out, int out_size) {
    const float* x    = (const float*)d_in[0];
    const int*   ei   = (const int*)d_in[1];    // int32 (JAX x64 disabled)
    const float* w    = (const float*)d_in[2];
    const float* W1   = (const float*)d_in[3];
    const float* b1   = (const float*)d_in[4];
    const float* W2   = (const float*)d_in[5];
    const float* b2   = (const float*)d_in[6];
    const float* Wout = (const float*)d_in[7];
    const float* bout = (const float*)d_in[8];
    float*       out  = (float*)d_out;

    const int n = in_sizes[0] / FDIM;   // 50000
    const int e = in_sizes[2];          // 800000

    const int TB = 256;
    int gemmGrid = (n + 63) / 64;
    int aggGrid  = (int)(((size_t)n * 8 + TB - 1) / TB);

    // prologue: bucket edges + weighted degree, dinv
    k_prep<<<(n + TB - 1) / TB, TB>>>(n);
    k_edge<<<(e + TB - 1) / TB, TB>>>(ei, w, e);
    k_dinv<<<(n + TB - 1) / TB, TB>>>(n);

    // layer 1
    k_gemm64<false><<<gemmGrid, 256>>>(x, b1, W1, n);
    k_agg_pull<<<aggGrid, TB>>>(n);

    // layer 2 (bias b1 + relu fused into GEMM load)
    k_gemm64<true><<<gemmGrid, 256>>>(x, b1, W2, n);
    k_agg_pull<<<aggGrid, TB>>>(n);

    // head: bias b2 + relu + GEMM->16 + softmax
    k_head<<<(n + 7) / 8, 128>>>(b2, Wout, bout, out, n);
}

// round 14
// speedup vs baseline: 1.3468x; 1.0644x over previous
#include <cuda_runtime.h>
#include <cuda_fp16.h>

#define NNODES 50000
#define NEDGES 800000
#define FDIM 64
#define NCLS 16
#define CAP 128   // per-node edge capacity (deg ~ Binomial(800k,1/50k); max ~45)

typedef unsigned long long ull;

// ---- device scratch (allocation-free; zero-initialized at load) ----
__device__ int    g_cnt[NNODES];                   // per-node fill counters (reset by agg2)
__device__ float  g_degw[NNODES];                  // weighted degree, from 0 (reset by agg2)
__device__ float  g_dinv[NNODES];
__device__ int2   g_edge[(size_t)NNODES * CAP];    // bucketed edges: {src, w bits}
__device__ __half g_bufAh[(size_t)NNODES * FDIM];  // GEMM outputs, fp16 (gather source)
__device__ float  g_bufB[(size_t)NNODES * FDIM];   // aggregated features, fp32

// ---------------- prologue ----------------
__global__ void k_edge(const int* __restrict__ ei,
                       const float* __restrict__ w, int e) {
    int i = blockIdx.x * blockDim.x + threadIdx.x;
    if (i < e) {
        int   r  = ei[i];
        int   c  = ei[e + i];
        float wv = w[i];
        atomicAdd(&g_degw[c], wv);
        int pos = atomicAdd(&g_cnt[c], 1);
        if (pos < CAP)
            g_edge[(size_t)c * CAP + pos] = make_int2(r, __float_as_int(wv));
    }
}

__global__ void k_dinv(int n) {
    int i = blockIdx.x * blockDim.x + threadIdx.x;
    if (i < n)
        g_dinv[i] = rsqrtf(1.0f + g_degw[i]);   // +1 = self-loop; always > 0
}

// ---------------- 64x64 GEMM: bufAh = fp16( act(X [+bias]) @ W ) ----------------
// 64 rows/block, 128 threads, 8 rows x 4 cols per thread, packed fma.rn.f32x2.
// Fill uses per-thread 4x4 register transpose -> STS.128 row-quads (no 16-way conflicts).
template <bool FROM_BUF>
__global__ void __launch_bounds__(128) k_gemm64(const float* __restrict__ Xext,
                         const float* __restrict__ bias,
                         const float* __restrict__ W, int n) {
    __shared__ __align__(16) float Ws[FDIM * FDIM];   // [k][c] row-major
    __shared__ __align__(16) float XsT[FDIM][68];     // [k][row], 64 rows + pad (272B stride, 16B-aligned)
    const int tid = threadIdx.x;                      // 0..127

    // W: straight float4 copy
    {
        const float4* W4 = (const float4*)W;
        float4* Ws4 = (float4*)Ws;
#pragma unroll
        for (int i = tid; i < FDIM * FDIM / 4; i += 128)
            Ws4[i] = W4[i];
    }

    const int row0 = blockIdx.x * 64;
    const float* X = FROM_BUF ? g_bufB : Xext;

    // ---- fill: coalesced loads, 4x4 register transpose, STS.128 stores ----
    {
        const int kq = tid & 15;          // k-quarter (4 floats)
        const int rg = tid >> 4;          // row-group of 8 (0..7)
        float4 b4 = make_float4(0.f, 0.f, 0.f, 0.f);
        if (FROM_BUF) b4 = *(const float4*)&bias[kq * 4];
#pragma unroll
        for (int h = 0; h < 2; h++) {
            const int rbase = rg * 8 + h * 4;
            float4 v[4];
#pragma unroll
            for (int j = 0; j < 4; j++) {
                int row = row0 + rbase + j;
                float4 t = make_float4(0.f, 0.f, 0.f, 0.f);
                if (row < n) t = *(const float4*)&X[(size_t)row * FDIM + kq * 4];
                if (FROM_BUF) {
                    t.x = fmaxf(t.x + b4.x, 0.f);
                    t.y = fmaxf(t.y + b4.y, 0.f);
                    t.z = fmaxf(t.z + b4.z, 0.f);
                    t.w = fmaxf(t.w + b4.w, 0.f);
                }
                v[j] = t;
            }
            *(float4*)&XsT[kq * 4 + 0][rbase] = make_float4(v[0].x, v[1].x, v[2].x, v[3].x);
            *(float4*)&XsT[kq * 4 + 1][rbase] = make_float4(v[0].y, v[1].y, v[2].y, v[3].y);
            *(float4*)&XsT[kq * 4 + 2][rbase] = make_float4(v[0].z, v[1].z, v[2].z, v[3].z);
            *(float4*)&XsT[kq * 4 + 3][rbase] = make_float4(v[0].w, v[1].w, v[2].w, v[3].w);
        }
    }
    __syncthreads();

    // ---- compute: 8 rows x 4 cols per thread ----
    const int c0 = (tid & 15) * 4;   // 4 output cols
    const int r0 = (tid >> 4) * 8;   // 8 rows within tile

    ull a0[4] = {0ull, 0ull, 0ull, 0ull};   // rows (r0,   r0+1)
    ull a1[4] = {0ull, 0ull, 0ull, 0ull};   // rows (r0+2, r0+3)
    ull a2[4] = {0ull, 0ull, 0ull, 0ull};   // rows (r0+4, r0+5)
    ull a3[4] = {0ull, 0ull, 0ull, 0ull};   // rows (r0+6, r0+7)

#pragma unroll
    for (int k = 0; k < FDIM; k++) {
        ulonglong2 avl = *(const ulonglong2*)&XsT[k][r0];      // rows r0..r0+3
        ulonglong2 avh = *(const ulonglong2*)&XsT[k][r0 + 4];  // rows r0+4..r0+7
        float4 bv = *(const float4*)&Ws[k * FDIM + c0];
        ull bd0, bd1, bd2, bd3;
        asm("mov.b64 %0, {%1, %1};" : "=l"(bd0) : "f"(bv.x));
        asm("mov.b64 %0, {%1, %1};" : "=l"(bd1) : "f"(bv.y));
        asm("mov.b64 %0, {%1, %1};" : "=l"(bd2) : "f"(bv.z));
        asm("mov.b64 %0, {%1, %1};" : "=l"(bd3) : "f"(bv.w));
        asm("fma.rn.f32x2 %0, %1, %2, %0;" : "+l"(a0[0]) : "l"(avl.x), "l"(bd0));
        asm("fma.rn.f32x2 %0, %1, %2, %0;" : "+l"(a0[1]) : "l"(avl.x), "l"(bd1));
        asm("fma.rn.f32x2 %0, %1, %2, %0;" : "+l"(a0[2]) : "l"(avl.x), "l"(bd2));
        asm("fma.rn.f32x2 %0, %1, %2, %0;" : "+l"(a0[3]) : "l"(avl.x), "l"(bd3));
        asm("fma.rn.f32x2 %0, %1, %2, %0;" : "+l"(a1[0]) : "l"(avl.y), "l"(bd0));
        asm("fma.rn.f32x2 %0, %1, %2, %0;" : "+l"(a1[1]) : "l"(avl.y), "l"(bd1));
        asm("fma.rn.f32x2 %0, %1, %2, %0;" : "+l"(a1[2]) : "l"(avl.y), "l"(bd2));
        asm("fma.rn.f32x2 %0, %1, %2, %0;" : "+l"(a1[3]) : "l"(avl.y), "l"(bd3));
        asm("fma.rn.f32x2 %0, %1, %2, %0;" : "+l"(a2[0]) : "l"(avh.x), "l"(bd0));
        asm("fma.rn.f32x2 %0, %1, %2, %0;" : "+l"(a2[1]) : "l"(avh.x), "l"(bd1));
        asm("fma.rn.f32x2 %0, %1, %2, %0;" : "+l"(a2[2]) : "l"(avh.x), "l"(bd2));
        asm("fma.rn.f32x2 %0, %1, %2, %0;" : "+l"(a2[3]) : "l"(avh.x), "l"(bd3));
        asm("fma.rn.f32x2 %0, %1, %2, %0;" : "+l"(a3[0]) : "l"(avh.y), "l"(bd0));
        asm("fma.rn.f32x2 %0, %1, %2, %0;" : "+l"(a3[1]) : "l"(avh.y), "l"(bd1));
        asm("fma.rn.f32x2 %0, %1, %2, %0;" : "+l"(a3[2]) : "l"(avh.y), "l"(bd2));
        asm("fma.rn.f32x2 %0, %1, %2, %0;" : "+l"(a3[3]) : "l"(avh.y), "l"(bd3));
    }

    // ---- epilogue: unpack row pairs, convert fp16, one 8B store per row ----
    const int rowb = row0 + r0;
#pragma unroll
    for (int p = 0; p < 4; p++) {
        ull* ap = (p == 0) ? a0 : (p == 1) ? a1 : (p == 2) ? a2 : a3;
        float lo[4], hi[4];
#pragma unroll
        for (int c = 0; c < 4; c++)
            asm("mov.b64 {%0, %1}, %2;" : "=f"(lo[c]), "=f"(hi[c]) : "l"(ap[c]));
        int r = rowb + 2 * p;
        if (r < n) {
            __half2 h[2];
            h[0] = __float22half2_rn(make_float2(lo[0], lo[1]));
            h[1] = __float22half2_rn(make_float2(lo[2], lo[3]));
            *(uint2*)&g_bufAh[(size_t)r * FDIM + c0] = *(uint2*)h;
        }
        if (r + 1 < n) {
            __half2 h[2];
            h[0] = __float22half2_rn(make_float2(hi[0], hi[1]));
            h[1] = __float22half2_rn(make_float2(hi[2], hi[3]));
            *(uint2*)&g_bufAh[(size_t)(r + 1) * FDIM + c0] = *(uint2*)h;
        }
    }
}

// fp16x8 gather helper: accumulate nv * bufAh[src][8q .. 8q+7] into acc[8] (fp32)
__device__ __forceinline__ void acc_half8(float* acc, float nv, uint4 u) {
    float2 f0 = __half22float2(*(__half2*)&u.x);
    float2 f1 = __half22float2(*(((__half2*)&u.x) + 1));
    float2 f2 = __half22float2(*(__half2*)&u.z);
    float2 f3 = __half22float2(*(((__half2*)&u.z) + 1));
    acc[0] += nv * f0.x;  acc[1] += nv * f0.y;
    acc[2] += nv * f1.x;  acc[3] += nv * f1.y;
    acc[4] += nv * f2.x;  acc[5] += nv * f2.y;
    acc[6] += nv * f3.x;  acc[7] += nv * f3.y;
}

// ---------------- pull aggregation: bufB[v] = dv*( sum dinv[src]*w*bufAh[src] + dv*bufAh[v] ) ----------------
// 8 lanes per node, one uint4 (8 halves) per lane; fp32 accumulation; unroll 4.
// RESET: last user of g_cnt/g_degw this call -> restore to zero for the next call/replay.
template <bool RESET>
__global__ void k_agg_pull(int n) {
    int gid = blockIdx.x * blockDim.x + threadIdx.x;
    int node = gid >> 3;
    int q    = gid & 7;
    if (node >= n) return;

    int cnt = g_cnt[node];
    if (cnt > CAP) cnt = CAP;
    float dv = g_dinv[node];
    const size_t base = (size_t)node * CAP;
    const uint4* selfp = reinterpret_cast<const uint4*>(g_bufAh + (size_t)node * FDIM) + q;

    float acc[8] = {0.f, 0.f, 0.f, 0.f, 0.f, 0.f, 0.f, 0.f};
    acc_half8(acc, dv, __ldg(selfp));

    int i = 0;
    for (; i + 4 <= cnt; i += 4) {
        int2 e0 = __ldg(g_edge + base + i + 0);
        int2 e1 = __ldg(g_edge + base + i + 1);
        int2 e2 = __ldg(g_edge + base + i + 2);
        int2 e3 = __ldg(g_edge + base + i + 3);
        float n0 = __ldg(g_dinv + e0.x) * __int_as_float(e0.y);
        float n1 = __ldg(g_dinv + e1.x) * __int_as_float(e1.y);
        float n2 = __ldg(g_dinv + e2.x) * __int_as_float(e2.y);
        float n3 = __ldg(g_dinv + e3.x) * __int_as_float(e3.y);
        uint4 u0 = __ldg(reinterpret_cast<const uint4*>(g_bufAh + (size_t)e0.x * FDIM) + q);
        uint4 u1 = __ldg(reinterpret_cast<const uint4*>(g_bufAh + (size_t)e1.x * FDIM) + q);
        uint4 u2 = __ldg(reinterpret_cast<const uint4*>(g_bufAh + (size_t)e2.x * FDIM) + q);
        uint4 u3 = __ldg(reinterpret_cast<const uint4*>(g_bufAh + (size_t)e3.x * FDIM) + q);
        acc_half8(acc, n0, u0);
        acc_half8(acc, n1, u1);
        acc_half8(acc, n2, u2);
        acc_half8(acc, n3, u3);
    }
    for (; i < cnt; i++) {
        int2 e0 = __ldg(g_edge + base + i);
        float n0 = __ldg(g_dinv + e0.x) * __int_as_float(e0.y);
        uint4 u0 = __ldg(reinterpret_cast<const uint4*>(g_bufAh + (size_t)e0.x * FDIM) + q);
        acc_half8(acc, n0, u0);
    }

    float4 o0 = make_float4(acc[0] * dv, acc[1] * dv, acc[2] * dv, acc[3] * dv);
    float4 o1 = make_float4(acc[4] * dv, acc[5] * dv, acc[6] * dv, acc[7] * dv);
    float4* dst = reinterpret_cast<float4*>(g_bufB + (size_t)node * FDIM) + q * 2;
    dst[0] = o0;
    dst[1] = o1;

    if (RESET && q == 0) {
        g_cnt[node]  = 0;
        g_degw[node] = 0.0f;
    }
}

// ---------------- head: relu(bufB + b2) @ Wout + bout -> softmax ----------------
__global__ void k_head(const float* __restrict__ b2,
                       const float* __restrict__ Wout,
                       const float* __restrict__ bout,
                       float* __restrict__ out, int n) {
    __shared__ float Ws[FDIM * NCLS];
    __shared__ float Hs[8][FDIM + 1];
    const int tid = threadIdx.x;   // 0..127

    for (int i = tid; i < FDIM * NCLS; i += 128) Ws[i] = Wout[i];

    int row0 = blockIdx.x * 8;
    for (int i = tid; i < 8 * FDIM; i += 128) {
        int rr = i >> 6, k = i & 63;
        int row = row0 + rr;
        float v = (row < n) ? g_bufB[(size_t)row * FDIM + k] : 0.0f;
        Hs[rr][k] = fmaxf(v + b2[k], 0.0f);
    }
    __syncthreads();

    int rr = tid >> 4;
    int c  = tid & 15;
    int row = row0 + rr;
    if (row < n) {
        float acc = bout[c];
#pragma unroll
        for (int k = 0; k < FDIM; k++)
            acc += Hs[rr][k] * Ws[k * NCLS + c];
        float m = acc;
#pragma unroll
        for (int off = 8; off; off >>= 1)
            m = fmaxf(m, __shfl_xor_sync(0xffffffffu, m, off, 16));
        float ex = __expf(acc - m);
        float s = ex;
#pragma unroll
        for (int off = 8; off; off >>= 1)
            s += __shfl_xor_sync(0xffffffffu, s, off, 16);
        out[(size_t)row * NCLS + c] = ex / s;
    }
}

// ---------------- launch ----------------
extern "C" void kernel_launch(void* const* d_in, const int* in_sizes, int n_in,
                              void* d_out, int out_size) {
    const float* x    = (const float*)d_in[0];
    const int*   ei   = (const int*)d_in[1];    // int32 (JAX x64 disabled)
    const float* w    = (const float*)d_in[2];
    const float* W1   = (const float*)d_in[3];
    const float* b1   = (const float*)d_in[4];
    const float* W2   = (const float*)d_in[5];
    const float* b2   = (const float*)d_in[6];
    const float* Wout = (const float*)d_in[7];
    const float* bout = (const float*)d_in[8];
    float*       out  = (float*)d_out;

    const int n = in_sizes[0] / FDIM;   // 50000
    const int e = in_sizes[2];          // 800000

    const int TB = 256;
    int gemmGrid = (n + 63) / 64;
    int aggGrid  = (int)(((size_t)n * 8 + TB - 1) / TB);

    // prologue: bucket edges + weighted degree (counters start at 0: zero-init
    // on first call, reset by agg2 on every call/replay), then dinv
    k_edge<<<(e + TB - 1) / TB, TB>>>(ei, w, e);
    k_dinv<<<(n + TB - 1) / TB, TB>>>(n);

    // layer 1
    k_gemm64<false><<<gemmGrid, 128>>>(x, b1, W1, n);
    k_agg_pull<false><<<aggGrid, TB>>>(n);

    // layer 2 (bias b1 + relu fused into GEMM load)
    k_gemm64<true><<<gemmGrid, 128>>>(x, b1, W2, n);
    k_agg_pull<true><<<aggGrid, TB>>>(n);   // resets g_cnt/g_degw for next call

    // head: bias b2 + relu + GEMM->16 + softmax
    k_head<<<(n + 7) / 8, 128>>>(b2, Wout, bout, out, n);
}